// round 1
// baseline (speedup 1.0000x reference)
#include <cuda_runtime.h>
#include <math.h>

#define GRID_D    24
#define N_ANCH    13824           // 24*24*24
#define TPB       256
#define ITERS     54              // N_ANCH / TPB
#define TOPK_N    60
#define NMS_TOPK  20
#define AVG_TOPN  7
#define SCORE_THR 0.15f
#define NMS_THR   0.05f
#define NBINS     64
#define CAND_MAX  1024

__global__ __launch_bounds__(TPB) void det_post_kernel(
    const float* __restrict__ Cls,
    const float* __restrict__ Shape,
    const float* __restrict__ Offset,
    float* __restrict__ Out)
{
    const int b   = blockIdx.x;
    const int tid = threadIdx.x;
    const float* cls = Cls    + (size_t)b * N_ANCH;
    const float* shp = Shape  + (size_t)b * 3 * N_ANCH;
    const float* off = Offset + (size_t)b * 3 * N_ANCH;

    __shared__ unsigned int       hist[NBINS];
    __shared__ unsigned long long keys[CAND_MAX];
    __shared__ int                s_cand;
    __shared__ int                s_bstar;
    __shared__ int                s_done;
    __shared__ float              detS[TOPK_N][8];
    __shared__ float              iouS[TOPK_N][TOPK_N];
    __shared__ unsigned long long s_availM, s_sel;
    __shared__ unsigned int       s_m0, s_m1;
    __shared__ int                s_idx, s_topn, s_any;

    // ---- Phase A: load Cls logits into registers (coalesced, single dense read) ----
    float xv[ITERS];
    #pragma unroll
    for (int k = 0; k < ITERS; k++) {
        xv[k] = cls[tid + k * TPB];
    }

    // ---- Phase B: adaptive tail histogram to find the 60th-largest logit bin ----
    // Window [L, L+3.2) with 64 bins of width 0.05; values >= top edge clamp to bin 63.
    // Start at L=2.0 (top ~2% of N(0,1) tail -> ~300 atomics/block). If fewer than 60
    // elements land at/above L, shift the window down deterministically and retry.
    float L = 2.0f;
    for (;;) {
        if (tid < NBINS) hist[tid] = 0u;
        __syncthreads();
        #pragma unroll
        for (int k = 0; k < ITERS; k++) {
            float x = xv[k];
            if (x >= L) {
                int bin = (int)((x - L) * 20.0f);
                bin = min(bin, NBINS - 1);
                atomicAdd(&hist[bin], 1u);
            }
        }
        __syncthreads();
        if (tid == 0) {
            unsigned int sfx = 0;
            int bstar = -1;
            for (int bb = NBINS - 1; bb >= 0; bb--) {
                sfx += hist[bb];
                if (sfx >= TOPK_N) { bstar = bb; break; }
            }
            s_bstar = bstar;
            s_done  = (bstar >= 0);
        }
        __syncthreads();
        if (s_done) break;
        L -= 3.2f;  // all threads compute identical L sequence
    }
    const int bstar = s_bstar;

    // ---- Phase C: collect candidate keys (score-bits desc, index asc tiebreak) ----
    if (tid == 0) s_cand = 0;
    __syncthreads();
    #pragma unroll
    for (int k = 0; k < ITERS; k++) {
        float x = xv[k];
        if (x >= L) {
            int bin = min((int)((x - L) * 20.0f), NBINS - 1);
            if (bin >= bstar) {
                float s = 1.0f / (1.0f + expf(-x));      // s in (0,1): bits order == float order
                unsigned int sb  = __float_as_uint(s);
                unsigned int idx = (unsigned int)(tid + k * TPB);
                unsigned long long key =
                    ((unsigned long long)sb << 32) | (unsigned long long)(0xFFFFFFFFu - idx);
                int pos = atomicAdd(&s_cand, 1);
                if (pos < CAND_MAX) keys[pos] = key;
            }
        }
    }
    __syncthreads();
    int C = min(s_cand, CAND_MAX);   // guaranteed >= 60 by construction

    int n = 64;
    while (n < C) n <<= 1;
    for (int i = C + tid; i < n; i += TPB) keys[i] = 0ull;
    __syncthreads();

    // ---- Phase D: bitonic sort descending over n keys ----
    for (int kk = 2; kk <= n; kk <<= 1) {
        for (int j = kk >> 1; j > 0; j >>= 1) {
            for (int l = tid; l < n; l += TPB) {
                int ixj = l ^ j;
                if (ixj > l) {
                    unsigned long long a = keys[l], c = keys[ixj];
                    bool descSeg = ((l & kk) == 0);
                    if (descSeg ? (a < c) : (a > c)) {
                        keys[l] = c; keys[ixj] = a;
                    }
                }
            }
            __syncthreads();
        }
    }

    // ---- Phase E: build det rows for top-60 (sparse gather of Shape/Offset) ----
    if (tid < TOPK_N) {
        unsigned long long key = keys[tid];
        unsigned int idx = 0xFFFFFFFFu - (unsigned int)(key & 0xFFFFFFFFull);
        float s = __uint_as_float((unsigned int)(key >> 32));
        float cz = 0.f, cy = 0.f, cx = 0.f, sz = 0.f, sy = 0.f, sx = 0.f;
        if (idx < N_ANCH) {
            int iz = (int)idx / (GRID_D * GRID_D);
            int iy = ((int)idx / GRID_D) % GRID_D;
            int ix = (int)idx % GRID_D;
            float oz = off[0 * N_ANCH + idx];
            float oy = off[1 * N_ANCH + idx];
            float ox = off[2 * N_ANCH + idx];
            cz = ((float)iz + oz) * 4.0f;
            cy = ((float)iy + oy) * 4.0f;
            cx = ((float)ix + ox) * 4.0f;
            sz = shp[0 * N_ANCH + idx];
            sy = shp[1 * N_ANCH + idx];
            sx = shp[2 * N_ANCH + idx];
        }
        detS[tid][0] = 1.0f; detS[tid][1] = s;
        detS[tid][2] = cz;   detS[tid][3] = cy; detS[tid][4] = cx;
        detS[tid][5] = sz;   detS[tid][6] = sy; detS[tid][7] = sx;
    }
    __syncthreads();

    // ---- Phase F: 60x60 IoU matrix ----
    for (int p = tid; p < TOPK_N * TOPK_N; p += TPB) {
        int i = p / TOPK_N, j = p % TOPK_N;
        float inter = 1.0f, voli = 1.0f, volj = 1.0f;
        #pragma unroll
        for (int d = 0; d < 3; d++) {
            float ci = detS[i][2 + d], si = detS[i][5 + d];
            float cj = detS[j][2 + d], sj = detS[j][5 + d];
            float loi = ci - 0.5f * si, hii = ci + 0.5f * si;
            float loj = cj - 0.5f * sj, hij = cj + 0.5f * sj;
            float w = fminf(hii, hij) - fmaxf(loi, loj);
            inter *= fmaxf(w, 0.0f);
            voli  *= si;
            volj  *= sj;
        }
        iouS[i][j] = inter / (voli + volj - inter);
    }

    // valid mask via ballots over the first 64 threads
    bool v = (tid < TOPK_N) && (detS[tid][1] > SCORE_THR);
    unsigned int vb = __ballot_sync(0xFFFFFFFFu, v);
    if (tid == 0)  s_m0 = vb;
    if (tid == 32) s_m1 = vb;
    __syncthreads();

    unsigned long long validM = 0ull, suppM = 0ull;
    if (tid == 0) {
        validM = (unsigned long long)s_m0 | ((unsigned long long)s_m1 << 32);
    }

    // ---- Phase G: 20-step greedy averaging NMS ----
    for (int step = 0; step < NMS_TOPK; step++) {
        if (tid == 0) {
            unsigned long long avail = validM & ~suppM;
            s_any    = (avail != 0ull) ? 1 : 0;
            s_idx    = avail ? (__ffsll((long long)avail) - 1) : 0;
            s_availM = avail;
        }
        __syncthreads();
        const int idx = s_idx;

        bool m = false;
        if (s_any && tid < TOPK_N) {
            bool av = (s_availM >> tid) & 1ull;
            m = av && (iouS[idx][tid] > NMS_THR || tid == idx);
        }
        unsigned int mb = __ballot_sync(0xFFFFFFFFu, m);
        if (tid == 0)  s_m0 = mb;
        if (tid == 32) s_m1 = mb;
        __syncthreads();

        if (tid == 0) {
            unsigned long long matched =
                (unsigned long long)s_m0 | ((unsigned long long)s_m1 << 32);
            int cnt  = __popcll(matched);
            int topn = min(cnt, AVG_TOPN);
            unsigned long long sel = 0ull, mm = matched;
            #pragma unroll
            for (int i = 0; i < AVG_TOPN; i++) {
                if (!mm) break;
                unsigned long long bit = mm & (~mm + 1ull);
                sel |= bit;
                mm ^= bit;
            }
            s_sel  = sel;
            s_topn = topn;
            if (s_any) suppM |= matched;
        }
        __syncthreads();

        if (tid < 8) {
            float r;
            if (!s_any) {
                r = -1.0f;
            } else if (s_topn > 1) {
                float sum = 0.0f;
                unsigned long long mm = s_sel;
                while (mm) {
                    int j = __ffsll((long long)mm) - 1;
                    mm &= mm - 1ull;
                    sum += detS[j][tid];
                }
                r = sum / (float)s_topn;
                if (tid == 0) r = 1.0f;
                if (tid == 1) r = detS[idx][1];
            } else {
                r = detS[idx][tid];
            }
            Out[((size_t)b * NMS_TOPK + step) * 8 + tid] = r;
        }
        __syncthreads();
    }
}

extern "C" void kernel_launch(void* const* d_in, const int* in_sizes, int n_in,
                              void* d_out, int out_size) {
    const float* Cls    = (const float*)d_in[0];
    const float* Shape  = (const float*)d_in[1];
    const float* Offset = (const float*)d_in[2];
    float*       Out    = (float*)d_out;
    int B = in_sizes[0] / N_ANCH;
    det_post_kernel<<<B, TPB>>>(Cls, Shape, Offset, Out);
}

// round 2
// speedup vs baseline: 1.7827x; 1.7827x over previous
#include <cuda_runtime.h>
#include <math.h>

#define GRID_D    24
#define N_ANCH    13824           // 24*24*24
#define NV4       3456            // N_ANCH / 4
#define TPB       256
#define V4_FULL   13              // 13*256 = 3328 float4s; remaining 128 handled by tid<128
#define TOPK_N    60
#define NMS_TOPK  20
#define AVG_TOPN  7
#define SCORE_THR 0.15f
#define NMS_THR   0.05f
#define CAND_MAX  2048

__global__ __launch_bounds__(TPB) void det_post_kernel(
    const float* __restrict__ Cls,
    const float* __restrict__ Shape,
    const float* __restrict__ Offset,
    float* __restrict__ Out)
{
    const int b   = blockIdx.x;
    const int tid = threadIdx.x;
    const float4* cls4 = (const float4*)(Cls + (size_t)b * N_ANCH);
    const float*  shp  = Shape  + (size_t)b * 3 * N_ANCH;
    const float*  off  = Offset + (size_t)b * 3 * N_ANCH;

    __shared__ unsigned long long keys[CAND_MAX];
    __shared__ int                s_cand;
    __shared__ float              detS[TOPK_N][8];
    __shared__ float              iouS[TOPK_N][TOPK_N];

    // ---- Phase A: single streaming pass, collect candidates above threshold L ----
    // L=2.2 keeps ~1.4% of N(0,1): ~192 candidates/image, >=60 with overwhelming
    // probability. Deterministic threshold adjustment (bisection-flavored) as a
    // fallback; retries hit L2 (whole Cls is 14MB, fits easily).
    float L = 2.2f, stepL = 0.5f;
    int   dir = 0;
    int   C = 0;
    for (int attempt = 0; attempt < 24; attempt++) {
        if (tid == 0) s_cand = 0;
        __syncthreads();

        #pragma unroll
        for (int k = 0; k < V4_FULL; k++) {
            int f = tid + k * TPB;
            float4 x4 = cls4[f];
            float xs[4] = {x4.x, x4.y, x4.z, x4.w};
            #pragma unroll
            for (int c = 0; c < 4; c++) {
                float x = xs[c];
                if (x > L) {
                    float s = 1.0f / (1.0f + expf(-x));
                    unsigned int sb  = __float_as_uint(s);
                    unsigned int idx = (unsigned int)(4 * f + c);
                    int pos = atomicAdd(&s_cand, 1);
                    if (pos < CAND_MAX)
                        keys[pos] = ((unsigned long long)sb << 32) |
                                    (unsigned long long)(0xFFFFFFFFu - idx);
                }
            }
        }
        if (tid < 128) {   // tail: float4 indices 3328..3455
            int f = V4_FULL * TPB + tid;
            float4 x4 = cls4[f];
            float xs[4] = {x4.x, x4.y, x4.z, x4.w};
            #pragma unroll
            for (int c = 0; c < 4; c++) {
                float x = xs[c];
                if (x > L) {
                    float s = 1.0f / (1.0f + expf(-x));
                    unsigned int sb  = __float_as_uint(s);
                    unsigned int idx = (unsigned int)(4 * f + c);
                    int pos = atomicAdd(&s_cand, 1);
                    if (pos < CAND_MAX)
                        keys[pos] = ((unsigned long long)sb << 32) |
                                    (unsigned long long)(0xFFFFFFFFu - idx);
                }
            }
        }
        __syncthreads();
        C = s_cand;
        if (C >= TOPK_N && C <= CAND_MAX) break;
        // all threads follow the identical deterministic L sequence
        if (C < TOPK_N) { if (dir > 0) stepL *= 0.5f; L -= stepL; dir = -1; }
        else            { if (dir < 0) stepL *= 0.5f; L += stepL; dir = +1; }
        __syncthreads();
    }
    C = min(C, CAND_MAX);

    int n = 64;
    while (n < C) n <<= 1;
    for (int i = C + tid; i < n; i += TPB) keys[i] = 0ull;
    __syncthreads();

    // ---- Phase B: bitonic sort descending over n keys (typically n=256) ----
    for (int kk = 2; kk <= n; kk <<= 1) {
        for (int j = kk >> 1; j > 0; j >>= 1) {
            for (int l = tid; l < n; l += TPB) {
                int ixj = l ^ j;
                if (ixj > l) {
                    unsigned long long a = keys[l], c = keys[ixj];
                    bool descSeg = ((l & kk) == 0);
                    if (descSeg ? (a < c) : (a > c)) {
                        keys[l] = c; keys[ixj] = a;
                    }
                }
            }
            __syncthreads();
        }
    }

    // ---- Phase C: build det rows for top-60 (sparse gather) ----
    if (tid < TOPK_N) {
        unsigned long long key = keys[tid];
        unsigned int idx = 0xFFFFFFFFu - (unsigned int)(key & 0xFFFFFFFFull);
        float s = __uint_as_float((unsigned int)(key >> 32));
        float cz = 0.f, cy = 0.f, cx = 0.f, sz = 0.f, sy = 0.f, sx = 0.f;
        if (idx < N_ANCH) {
            int iz = (int)idx / (GRID_D * GRID_D);
            int iy = ((int)idx / GRID_D) % GRID_D;
            int ix = (int)idx % GRID_D;
            float oz = off[0 * N_ANCH + idx];
            float oy = off[1 * N_ANCH + idx];
            float ox = off[2 * N_ANCH + idx];
            cz = ((float)iz + oz) * 4.0f;
            cy = ((float)iy + oy) * 4.0f;
            cx = ((float)ix + ox) * 4.0f;
            sz = shp[0 * N_ANCH + idx];
            sy = shp[1 * N_ANCH + idx];
            sx = shp[2 * N_ANCH + idx];
        }
        detS[tid][0] = 1.0f; detS[tid][1] = s;
        detS[tid][2] = cz;   detS[tid][3] = cy; detS[tid][4] = cx;
        detS[tid][5] = sz;   detS[tid][6] = sy; detS[tid][7] = sx;
    }
    __syncthreads();

    // ---- Phase D: 60x60 IoU matrix ----
    for (int p = tid; p < TOPK_N * TOPK_N; p += TPB) {
        int i = p / TOPK_N, j = p % TOPK_N;
        float inter = 1.0f, voli = 1.0f, volj = 1.0f;
        #pragma unroll
        for (int d = 0; d < 3; d++) {
            float ci = detS[i][2 + d], si = detS[i][5 + d];
            float cj = detS[j][2 + d], sj = detS[j][5 + d];
            float loi = ci - 0.5f * si, hii = ci + 0.5f * si;
            float loj = cj - 0.5f * sj, hij = cj + 0.5f * sj;
            float w = fminf(hii, hij) - fmaxf(loi, loj);
            inter *= fmaxf(w, 0.0f);
            voli  *= si;
            volj  *= sj;
        }
        iouS[i][j] = inter / (voli + volj - inter);
    }
    __syncthreads();

    // ---- Phase E: 20-step greedy averaging NMS, entirely in warp 0 ----
    if (tid < 32) {
        const int lane = tid;
        const int r0 = lane, r1 = lane + 32;
        bool v0 = (detS[r0][1] > SCORE_THR);
        bool v1 = (r1 < TOPK_N) && (detS[r1][1] > SCORE_THR);
        unsigned int b0 = __ballot_sync(0xFFFFFFFFu, v0);
        unsigned int b1 = __ballot_sync(0xFFFFFFFFu, v1);
        unsigned long long validM =
            (unsigned long long)b0 | ((unsigned long long)b1 << 32);
        unsigned long long supp = 0ull;

        for (int step = 0; step < NMS_TOPK; step++) {
            unsigned long long avail = validM & ~supp;
            bool any = (avail != 0ull);
            int  idx = any ? (__ffsll((long long)avail) - 1) : 0;

            bool m0 = any && ((avail >> r0) & 1ull) &&
                      (iouS[idx][r0] > NMS_THR || r0 == idx);
            bool m1 = any && (r1 < TOPK_N) && ((avail >> r1) & 1ull) &&
                      (iouS[idx][r1] > NMS_THR || r1 == idx);
            unsigned int mb0 = __ballot_sync(0xFFFFFFFFu, m0);
            unsigned int mb1 = __ballot_sync(0xFFFFFFFFu, m1);
            unsigned long long matched =
                (unsigned long long)mb0 | ((unsigned long long)mb1 << 32);
            supp |= matched;

            int cnt  = __popcll(matched);
            int topn = min(cnt, AVG_TOPN);
            unsigned long long sel = 0ull, mm = matched;
            #pragma unroll
            for (int i = 0; i < AVG_TOPN; i++) {
                if (!mm) break;
                unsigned long long bit = mm & (~mm + 1ull);
                sel |= bit;
                mm ^= bit;
            }

            if (lane < 8) {
                float r;
                if (!any) {
                    r = -1.0f;
                } else if (topn > 1) {
                    float sum = 0.0f;
                    unsigned long long s2 = sel;
                    while (s2) {
                        int j = __ffsll((long long)s2) - 1;
                        s2 &= s2 - 1ull;
                        sum += detS[j][lane];
                    }
                    r = sum / (float)topn;
                    if (lane == 0) r = 1.0f;
                    if (lane == 1) r = detS[idx][1];
                } else {
                    r = detS[idx][lane];
                }
                Out[((size_t)b * NMS_TOPK + step) * 8 + lane] = r;
            }
        }
    }
}

extern "C" void kernel_launch(void* const* d_in, const int* in_sizes, int n_in,
                              void* d_out, int out_size) {
    const float* Cls    = (const float*)d_in[0];
    const float* Shape  = (const float*)d_in[1];
    const float* Offset = (const float*)d_in[2];
    float*       Out    = (float*)d_out;
    int B = in_sizes[0] / N_ANCH;
    det_post_kernel<<<B, TPB>>>(Cls, Shape, Offset, Out);
}

// round 3
// speedup vs baseline: 1.8044x; 1.0122x over previous
#include <cuda_runtime.h>
#include <math.h>

#define GRID_D    24
#define N_ANCH    13824           // 24*24*24
#define NV4       3456            // N_ANCH / 4
#define TPB       256
#define TOPK_N    60
#define NMS_TOPK  20
#define AVG_TOPN  7
#define SCORE_THR 0.15f
#define NMS_THR   0.05f
#define THRESH_L  2.2f
#define SPLIT     4
#define SEG_F4    864             // NV4 / SPLIT
#define SEG_CAP   512
#define CAND_MAX  2048            // SPLIT * SEG_CAP
#define MAX_B     256

// Per-image, per-part candidate scratch. Counts are written fresh every run
// (no accumulation), so no init pass is needed.
__device__ unsigned long long g_keys[MAX_B][SPLIT][SEG_CAP];
__device__ int                g_cnt[MAX_B][SPLIT];

__device__ __forceinline__ unsigned long long make_key(float x, unsigned int idx) {
    float s = 1.0f / (1.0f + expf(-x));               // s in (0,1): float order == bit order
    return ((unsigned long long)__float_as_uint(s) << 32) |
           (unsigned long long)(0xFFFFFFFFu - idx);
}

// ---------------- Kernel 1: high-occupancy streaming scan ----------------
__global__ __launch_bounds__(TPB) void scan_kernel(const float* __restrict__ Cls)
{
    const int part = blockIdx.x;
    const int b    = blockIdx.y;
    const int tid  = threadIdx.x;
    const float4* cls4 = (const float4*)(Cls + (size_t)b * N_ANCH);

    __shared__ int s_pos;
    if (tid == 0) s_pos = 0;
    __syncthreads();

    const int base = part * SEG_F4;
    #pragma unroll
    for (int k = 0; k < 4; k++) {                     // 4*256 = 1024 >= 864
        int r = tid + k * TPB;
        if (r < SEG_F4) {
            int f = base + r;
            float4 x4 = cls4[f];
            float xs[4] = {x4.x, x4.y, x4.z, x4.w};
            #pragma unroll
            for (int c = 0; c < 4; c++) {
                if (xs[c] > THRESH_L) {
                    int pos = atomicAdd(&s_pos, 1);
                    if (pos < SEG_CAP)
                        g_keys[b][part][pos] = make_key(xs[c], (unsigned int)(4 * f + c));
                }
            }
        }
    }
    __syncthreads();
    if (tid == 0) g_cnt[b][part] = s_pos;             // raw count (may exceed cap -> fallback)
}

// ---------------- Kernel 2: per-image sort + NMS ----------------
__global__ __launch_bounds__(TPB) void nms_kernel(
    const float* __restrict__ Cls,
    const float* __restrict__ Shape,
    const float* __restrict__ Offset,
    float* __restrict__ Out)
{
    const int b   = blockIdx.x;
    const int tid = threadIdx.x;
    const float* shp = Shape  + (size_t)b * 3 * N_ANCH;
    const float* off = Offset + (size_t)b * 3 * N_ANCH;

    __shared__ unsigned long long keys[CAND_MAX];
    __shared__ int                s_cand;
    __shared__ float              detS[TOPK_N][8];
    __shared__ float              iouS[TOPK_N][TOPK_N];

    // ---- compact segments ----
    int cnts[SPLIT], offs[SPLIT];
    int C = 0; bool overflow = false;
    #pragma unroll
    for (int p = 0; p < SPLIT; p++) {
        int c = g_cnt[b][p];
        if (c > SEG_CAP) { overflow = true; c = SEG_CAP; }
        cnts[p] = c; offs[p] = C; C += c;
    }
    #pragma unroll
    for (int p = 0; p < SPLIT; p++) {
        for (int i = tid; i < cnts[p]; i += TPB)
            keys[offs[p] + i] = g_keys[b][p][i];
    }
    __syncthreads();

    // ---- deterministic fallback: rescan this image with adaptive threshold ----
    if (overflow || C < TOPK_N) {
        const float4* cls4 = (const float4*)(Cls + (size_t)b * N_ANCH);
        float L = THRESH_L, stepL = 0.5f;
        int dir = 0;
        for (int attempt = 0; attempt < 24; attempt++) {
            if (tid == 0) s_cand = 0;
            __syncthreads();
            for (int f = tid; f < NV4; f += TPB) {
                float4 x4 = cls4[f];
                float xs[4] = {x4.x, x4.y, x4.z, x4.w};
                #pragma unroll
                for (int c = 0; c < 4; c++) {
                    if (xs[c] > L) {
                        int pos = atomicAdd(&s_cand, 1);
                        if (pos < CAND_MAX)
                            keys[pos] = make_key(xs[c], (unsigned int)(4 * f + c));
                    }
                }
            }
            __syncthreads();
            C = s_cand;
            if (C >= TOPK_N && C <= CAND_MAX) break;
            if (C < TOPK_N) { if (dir > 0) stepL *= 0.5f; L -= stepL; dir = -1; }
            else            { if (dir < 0) stepL *= 0.5f; L += stepL; dir = +1; }
            __syncthreads();
        }
        C = min(C, CAND_MAX);
    }

    int n = 64;
    while (n < C) n <<= 1;
    for (int i = C + tid; i < n; i += TPB) keys[i] = 0ull;
    __syncthreads();

    // ---- bitonic sort descending (typically n=256) ----
    for (int kk = 2; kk <= n; kk <<= 1) {
        for (int j = kk >> 1; j > 0; j >>= 1) {
            for (int l = tid; l < n; l += TPB) {
                int ixj = l ^ j;
                if (ixj > l) {
                    unsigned long long a = keys[l], c = keys[ixj];
                    bool descSeg = ((l & kk) == 0);
                    if (descSeg ? (a < c) : (a > c)) {
                        keys[l] = c; keys[ixj] = a;
                    }
                }
            }
            __syncthreads();
        }
    }

    // ---- build det rows for top-60 (sparse gather) ----
    if (tid < TOPK_N) {
        unsigned long long key = keys[tid];
        unsigned int idx = 0xFFFFFFFFu - (unsigned int)(key & 0xFFFFFFFFull);
        float s = __uint_as_float((unsigned int)(key >> 32));
        float cz = 0.f, cy = 0.f, cx = 0.f, sz = 0.f, sy = 0.f, sx = 0.f;
        if (idx < N_ANCH) {
            int iz = (int)idx / (GRID_D * GRID_D);
            int iy = ((int)idx / GRID_D) % GRID_D;
            int ix = (int)idx % GRID_D;
            cz = ((float)iz + off[0 * N_ANCH + idx]) * 4.0f;
            cy = ((float)iy + off[1 * N_ANCH + idx]) * 4.0f;
            cx = ((float)ix + off[2 * N_ANCH + idx]) * 4.0f;
            sz = shp[0 * N_ANCH + idx];
            sy = shp[1 * N_ANCH + idx];
            sx = shp[2 * N_ANCH + idx];
        }
        detS[tid][0] = 1.0f; detS[tid][1] = s;
        detS[tid][2] = cz;   detS[tid][3] = cy; detS[tid][4] = cx;
        detS[tid][5] = sz;   detS[tid][6] = sy; detS[tid][7] = sx;
    }
    __syncthreads();

    // ---- 60x60 IoU matrix ----
    for (int p = tid; p < TOPK_N * TOPK_N; p += TPB) {
        int i = p / TOPK_N, j = p % TOPK_N;
        float inter = 1.0f, voli = 1.0f, volj = 1.0f;
        #pragma unroll
        for (int d = 0; d < 3; d++) {
            float ci = detS[i][2 + d], si = detS[i][5 + d];
            float cj = detS[j][2 + d], sj = detS[j][5 + d];
            float loi = ci - 0.5f * si, hii = ci + 0.5f * si;
            float loj = cj - 0.5f * sj, hij = cj + 0.5f * sj;
            float w = fminf(hii, hij) - fmaxf(loi, loj);
            inter *= fmaxf(w, 0.0f);
            voli  *= si;
            volj  *= sj;
        }
        iouS[i][j] = inter / (voli + volj - inter);
    }
    __syncthreads();

    // ---- 20-step greedy averaging NMS, entirely in warp 0 ----
    if (tid < 32) {
        const int lane = tid;
        const int r0 = lane, r1 = lane + 32;
        bool v0 = (detS[r0][1] > SCORE_THR);
        bool v1 = (r1 < TOPK_N) && (detS[r1][1] > SCORE_THR);
        unsigned int b0 = __ballot_sync(0xFFFFFFFFu, v0);
        unsigned int b1 = __ballot_sync(0xFFFFFFFFu, v1);
        unsigned long long validM =
            (unsigned long long)b0 | ((unsigned long long)b1 << 32);
        unsigned long long supp = 0ull;

        for (int step = 0; step < NMS_TOPK; step++) {
            unsigned long long avail = validM & ~supp;
            bool any = (avail != 0ull);
            int  idx = any ? (__ffsll((long long)avail) - 1) : 0;

            bool m0 = any && ((avail >> r0) & 1ull) &&
                      (iouS[idx][r0] > NMS_THR || r0 == idx);
            bool m1 = any && (r1 < TOPK_N) && ((avail >> r1) & 1ull) &&
                      (iouS[idx][r1] > NMS_THR || r1 == idx);
            unsigned int mb0 = __ballot_sync(0xFFFFFFFFu, m0);
            unsigned int mb1 = __ballot_sync(0xFFFFFFFFu, m1);
            unsigned long long matched =
                (unsigned long long)mb0 | ((unsigned long long)mb1 << 32);
            supp |= matched;

            int cnt  = __popcll(matched);
            int topn = min(cnt, AVG_TOPN);
            unsigned long long sel = 0ull, mm = matched;
            #pragma unroll
            for (int i = 0; i < AVG_TOPN; i++) {
                if (!mm) break;
                unsigned long long bit = mm & (~mm + 1ull);
                sel |= bit;
                mm ^= bit;
            }

            if (lane < 8) {
                float r;
                if (!any) {
                    r = -1.0f;
                } else if (topn > 1) {
                    float sum = 0.0f;
                    unsigned long long s2 = sel;
                    while (s2) {
                        int j = __ffsll((long long)s2) - 1;
                        s2 &= s2 - 1ull;
                        sum += detS[j][lane];
                    }
                    r = sum / (float)topn;
                    if (lane == 0) r = 1.0f;
                    if (lane == 1) r = detS[idx][1];
                } else {
                    r = detS[idx][lane];
                }
                Out[((size_t)b * NMS_TOPK + step) * 8 + lane] = r;
            }
        }
    }
}

extern "C" void kernel_launch(void* const* d_in, const int* in_sizes, int n_in,
                              void* d_out, int out_size) {
    const float* Cls    = (const float*)d_in[0];
    const float* Shape  = (const float*)d_in[1];
    const float* Offset = (const float*)d_in[2];
    float*       Out    = (float*)d_out;
    int B = in_sizes[0] / N_ANCH;
    dim3 g1(SPLIT, B);
    scan_kernel<<<g1, TPB>>>(Cls);
    nms_kernel<<<B, TPB>>>(Cls, Shape, Offset, Out);
}

// round 4
// speedup vs baseline: 2.0741x; 1.1494x over previous
#include <cuda_runtime.h>
#include <math.h>

#define GRID_D    24
#define N_ANCH    13824           // 24*24*24
#define NV4       3456            // N_ANCH / 4
#define TPB       256
#define TOPK_N    60
#define NMS_TOPK  20
#define AVG_TOPN  7
#define SCORE_THR 0.15f
#define NMS_THR   0.05f
#define THRESH_L  2.2f
#define SPLIT     4
#define SEG_F4    864             // NV4 / SPLIT
#define SEG_CAP   512
#define CAND_MAX  2048            // SPLIT * SEG_CAP
#define MAX_B     256

// Per-image, per-part candidate scratch. Counts are overwritten every run.
__device__ unsigned long long g_keys[MAX_B][SPLIT][SEG_CAP];
__device__ int                g_cnt[MAX_B][SPLIT];

__device__ __forceinline__ unsigned long long make_key(float x, unsigned int idx) {
    float s = 1.0f / (1.0f + expf(-x));               // s in (0,1): float order == bit order
    return ((unsigned long long)__float_as_uint(s) << 32) |
           (unsigned long long)(0xFFFFFFFFu - idx);
}

// ---------------- Kernel 1: high-occupancy streaming scan ----------------
__global__ __launch_bounds__(TPB) void scan_kernel(const float* __restrict__ Cls)
{
    const int part = blockIdx.x;
    const int b    = blockIdx.y;
    const int tid  = threadIdx.x;
    const float4* cls4 = (const float4*)(Cls + (size_t)b * N_ANCH);

    __shared__ int s_pos;
    if (tid == 0) s_pos = 0;
    __syncthreads();

    const int base = part * SEG_F4;
    #pragma unroll
    for (int k = 0; k < 4; k++) {                     // 4*256 = 1024 >= 864
        int r = tid + k * TPB;
        if (r < SEG_F4) {
            int f = base + r;
            float4 x4 = cls4[f];
            float xs[4] = {x4.x, x4.y, x4.z, x4.w};
            #pragma unroll
            for (int c = 0; c < 4; c++) {
                if (xs[c] > THRESH_L) {
                    int pos = atomicAdd(&s_pos, 1);
                    if (pos < SEG_CAP)
                        g_keys[b][part][pos] = make_key(xs[c], (unsigned int)(4 * f + c));
                }
            }
        }
    }
    __syncthreads();
    if (tid == 0) g_cnt[b][part] = s_pos;             // raw count (may exceed cap -> fallback)
}

// ---------------- Kernel 2: per-image rank-select + NMS ----------------
__global__ __launch_bounds__(TPB) void nms_kernel(
    const float* __restrict__ Cls,
    const float* __restrict__ Shape,
    const float* __restrict__ Offset,
    float* __restrict__ Out)
{
    const int b   = blockIdx.x;
    const int tid = threadIdx.x;
    const float* shp = Shape  + (size_t)b * 3 * N_ANCH;
    const float* off = Offset + (size_t)b * 3 * N_ANCH;

    __shared__ unsigned long long keys[CAND_MAX];
    __shared__ int                s_cand;
    __shared__ float              detS[TOPK_N][8];
    __shared__ float              iouS[TOPK_N][TOPK_N];

    // pre-init det rows to "empty" (score 0 -> invalid); only hit if fallback
    // cannot reach 60 candidates (practically never).
    if (tid < TOPK_N) {
        detS[tid][0] = 1.0f;
        #pragma unroll
        for (int q = 1; q < 8; q++) detS[tid][q] = 0.0f;
    }

    // ---- compact segments ----
    int cnts[SPLIT], offs[SPLIT];
    int C = 0; bool overflow = false;
    #pragma unroll
    for (int p = 0; p < SPLIT; p++) {
        int c = g_cnt[b][p];
        if (c > SEG_CAP) { overflow = true; c = SEG_CAP; }
        cnts[p] = c; offs[p] = C; C += c;
    }
    #pragma unroll
    for (int p = 0; p < SPLIT; p++) {
        for (int i = tid; i < cnts[p]; i += TPB)
            keys[offs[p] + i] = g_keys[b][p][i];
    }
    __syncthreads();

    // ---- deterministic fallback: rescan this image with adaptive threshold ----
    if (overflow || C < TOPK_N) {
        const float4* cls4 = (const float4*)(Cls + (size_t)b * N_ANCH);
        float L = THRESH_L, stepL = 0.5f;
        int dir = 0;
        for (int attempt = 0; attempt < 24; attempt++) {
            if (tid == 0) s_cand = 0;
            __syncthreads();
            for (int f = tid; f < NV4; f += TPB) {
                float4 x4 = cls4[f];
                float xs[4] = {x4.x, x4.y, x4.z, x4.w};
                #pragma unroll
                for (int c = 0; c < 4; c++) {
                    if (xs[c] > L) {
                        int pos = atomicAdd(&s_cand, 1);
                        if (pos < CAND_MAX)
                            keys[pos] = make_key(xs[c], (unsigned int)(4 * f + c));
                    }
                }
            }
            __syncthreads();
            C = s_cand;
            if (C >= TOPK_N && C <= CAND_MAX) break;
            if (C < TOPK_N) { if (dir > 0) stepL *= 0.5f; L -= stepL; dir = -1; }
            else            { if (dir < 0) stepL *= 0.5f; L += stepL; dir = +1; }
            __syncthreads();
        }
        C = min(C, CAND_MAX);
    }

    // ---- rank-based top-60 selection (keys are all distinct) ----
    // rank_i = #{j: key_j > key_i}; scatter candidate i to detS[rank_i] if rank<60.
    for (int i = tid; i < C; i += TPB) {
        unsigned long long myKey = keys[i];
        int rank = 0;
        int j = 0;
        for (; j + 4 <= C; j += 4) {
            rank += (keys[j]     > myKey);
            rank += (keys[j + 1] > myKey);
            rank += (keys[j + 2] > myKey);
            rank += (keys[j + 3] > myKey);
        }
        for (; j < C; j++) rank += (keys[j] > myKey);

        if (rank < TOPK_N) {
            unsigned int idx = 0xFFFFFFFFu - (unsigned int)(myKey & 0xFFFFFFFFull);
            float s = __uint_as_float((unsigned int)(myKey >> 32));
            int iz = (int)idx / (GRID_D * GRID_D);
            int iy = ((int)idx / GRID_D) % GRID_D;
            int ix = (int)idx % GRID_D;
            float cz = ((float)iz + off[0 * N_ANCH + idx]) * 4.0f;
            float cy = ((float)iy + off[1 * N_ANCH + idx]) * 4.0f;
            float cx = ((float)ix + off[2 * N_ANCH + idx]) * 4.0f;
            float sz = shp[0 * N_ANCH + idx];
            float sy = shp[1 * N_ANCH + idx];
            float sx = shp[2 * N_ANCH + idx];
            detS[rank][0] = 1.0f; detS[rank][1] = s;
            detS[rank][2] = cz;   detS[rank][3] = cy; detS[rank][4] = cx;
            detS[rank][5] = sz;   detS[rank][6] = sy; detS[rank][7] = sx;
        }
    }
    __syncthreads();

    // ---- 60x60 IoU matrix ----
    for (int p = tid; p < TOPK_N * TOPK_N; p += TPB) {
        int i = p / TOPK_N, j = p % TOPK_N;
        float inter = 1.0f, voli = 1.0f, volj = 1.0f;
        #pragma unroll
        for (int d = 0; d < 3; d++) {
            float ci = detS[i][2 + d], si = detS[i][5 + d];
            float cj = detS[j][2 + d], sj = detS[j][5 + d];
            float loi = ci - 0.5f * si, hii = ci + 0.5f * si;
            float loj = cj - 0.5f * sj, hij = cj + 0.5f * sj;
            float w = fminf(hii, hij) - fmaxf(loi, loj);
            inter *= fmaxf(w, 0.0f);
            voli  *= si;
            volj  *= sj;
        }
        iouS[i][j] = inter / (voli + volj - inter);
    }
    __syncthreads();

    // ---- 20-step greedy averaging NMS, entirely in warp 0 ----
    if (tid < 32) {
        const int lane = tid;
        const int r0 = lane, r1 = lane + 32;
        bool v0 = (detS[r0][1] > SCORE_THR);
        bool v1 = (r1 < TOPK_N) && (detS[r1][1] > SCORE_THR);
        unsigned int b0 = __ballot_sync(0xFFFFFFFFu, v0);
        unsigned int b1 = __ballot_sync(0xFFFFFFFFu, v1);
        unsigned long long validM =
            (unsigned long long)b0 | ((unsigned long long)b1 << 32);
        unsigned long long supp = 0ull;

        for (int step = 0; step < NMS_TOPK; step++) {
            unsigned long long avail = validM & ~supp;
            bool any = (avail != 0ull);
            int  idx = any ? (__ffsll((long long)avail) - 1) : 0;

            bool m0 = any && ((avail >> r0) & 1ull) &&
                      (iouS[idx][r0] > NMS_THR || r0 == idx);
            bool m1 = any && (r1 < TOPK_N) && ((avail >> r1) & 1ull) &&
                      (iouS[idx][r1] > NMS_THR || r1 == idx);
            unsigned int mb0 = __ballot_sync(0xFFFFFFFFu, m0);
            unsigned int mb1 = __ballot_sync(0xFFFFFFFFu, m1);
            unsigned long long matched =
                (unsigned long long)mb0 | ((unsigned long long)mb1 << 32);
            supp |= matched;

            int cnt  = __popcll(matched);
            int topn = min(cnt, AVG_TOPN);
            unsigned long long sel = 0ull, mm = matched;
            #pragma unroll
            for (int i = 0; i < AVG_TOPN; i++) {
                if (!mm) break;
                unsigned long long bit = mm & (~mm + 1ull);
                sel |= bit;
                mm ^= bit;
            }

            if (lane < 8) {
                float r;
                if (!any) {
                    r = -1.0f;
                } else if (topn > 1) {
                    float sum = 0.0f;
                    unsigned long long s2 = sel;
                    while (s2) {
                        int j = __ffsll((long long)s2) - 1;
                        s2 &= s2 - 1ull;
                        sum += detS[j][lane];
                    }
                    r = sum / (float)topn;
                    if (lane == 0) r = 1.0f;
                    if (lane == 1) r = detS[idx][1];
                } else {
                    r = detS[idx][lane];
                }
                Out[((size_t)b * NMS_TOPK + step) * 8 + lane] = r;
            }
        }
    }
}

extern "C" void kernel_launch(void* const* d_in, const int* in_sizes, int n_in,
                              void* d_out, int out_size) {
    const float* Cls    = (const float*)d_in[0];
    const float* Shape  = (const float*)d_in[1];
    const float* Offset = (const float*)d_in[2];
    float*       Out    = (float*)d_out;
    int B = in_sizes[0] / N_ANCH;
    dim3 g1(SPLIT, B);
    scan_kernel<<<g1, TPB>>>(Cls);
    nms_kernel<<<B, TPB>>>(Cls, Shape, Offset, Out);
}